// round 9
// baseline (speedup 1.0000x reference)
#include <cuda_runtime.h>

// Problem constants
#define DIMV 768
#define BB   8
#define NT   2048

// GEMM tiling
#define BM 128
#define BN 128
#define BK 16
#define LDSM 132   // BM + 4 pad: keeps 16B alignment, avoids bank conflicts

// ---------------------------------------------------------------------------
// Scratch (device globals: allocation-free per harness rules)
// ---------------------------------------------------------------------------
__device__ float g_H0[BB * NT * DIMV];       // H for x2: exp(x)/sqrt(rowsum)
__device__ float g_H1[BB * NT * DIMV];       // H for x3
__device__ float g_rs0[BB * NT];             // sqrt(rowsum_true) per row
__device__ float g_rs1[BB * NT];
__device__ float g_part0[16 * BB * DIMV];    // partial column sums
__device__ float g_part1[16 * BB * DIMV];
__device__ float g_cs0[BB * DIMV];           // colsum of exp(x2)
__device__ float g_cs1[BB * DIMV];
__device__ float g_M0[BB * DIMV * DIMV];     // M1 = key1^T query1
__device__ float g_M1[BB * DIMV * DIMV];     // M2
__device__ float g_WT0[DIMV * DIMV];         // W1 transposed
__device__ float g_WT1[DIMV * DIMV];         // W2 transposed
__device__ float g_Cmat[BB * DIMV * DIMV];   // f*(M1 W1^T + M2 W2^T)

// ---------------------------------------------------------------------------
// Row softmax -> H[m,d] = exp(x[m,d]) / sqrt(S[m]),  rs[m] = sqrt(S[m])
// (S = true rowsum of exp; computed max-shifted for safety)
// One block per row (768 elems, 256 threads, 3 per thread).
// ---------------------------------------------------------------------------
__global__ __launch_bounds__(256) void row_softmax_kernel(const float* __restrict__ x, int sel) {
    float* H  = sel ? g_H1  : g_H0;
    float* rs = sel ? g_rs1 : g_rs0;
    size_t row = blockIdx.x;
    const float* xr = x + row * DIMV;
    int tid = threadIdx.x;

    float v0 = xr[tid], v1 = xr[tid + 256], v2 = xr[tid + 512];
    float m = fmaxf(v0, fmaxf(v1, v2));

    __shared__ float red[8];
    #pragma unroll
    for (int o = 16; o > 0; o >>= 1) m = fmaxf(m, __shfl_xor_sync(0xffffffffu, m, o));
    if ((tid & 31) == 0) red[tid >> 5] = m;
    __syncthreads();
    float bm = red[0];
    #pragma unroll
    for (int i = 1; i < 8; i++) bm = fmaxf(bm, red[i]);

    float e0 = expf(v0 - bm), e1 = expf(v1 - bm), e2 = expf(v2 - bm);
    float s = e0 + e1 + e2;
    #pragma unroll
    for (int o = 16; o > 0; o >>= 1) s += __shfl_xor_sync(0xffffffffu, s, o);
    __syncthreads();                       // before reusing red[]
    if ((tid & 31) == 0) red[tid >> 5] = s;
    __syncthreads();
    float S = 0.f;
    #pragma unroll
    for (int i = 0; i < 8; i++) S += red[i];

    // H = e * exp(bm/2)/sqrt(S_shift);  rs = exp(bm/2)*sqrt(S_shift)
    float half = expf(0.5f * bm);
    float scale = half * rsqrtf(S);
    float* hr = H + row * DIMV;
    hr[tid]       = e0 * scale;
    hr[tid + 256] = e1 * scale;
    hr[tid + 512] = e2 * scale;
    if (tid == 0) rs[row] = half * sqrtf(S);
}

// ---------------------------------------------------------------------------
// Column sums of exp(x) = sum_m H[m,d]*rs[m].  Partial over 128-row chunks.
// grid (3, BB, 16), 256 threads
// ---------------------------------------------------------------------------
__global__ __launch_bounds__(256) void colsum_part_kernel(int sel) {
    const float* H  = sel ? g_H1  : g_H0;
    const float* rs = sel ? g_rs1 : g_rs0;
    float* part = sel ? g_part1 : g_part0;
    int d = blockIdx.x * 256 + threadIdx.x;
    int b = blockIdx.y, z = blockIdx.z;
    size_t rowbase = (size_t)b * NT + (size_t)z * 128;
    const float* hp = H + rowbase * DIMV + d;
    const float* rp = rs + rowbase;
    float acc = 0.f;
    #pragma unroll 4
    for (int m = 0; m < 128; m++)
        acc = fmaf(hp[(size_t)m * DIMV], rp[m], acc);
    part[((size_t)z * BB + b) * DIMV + d] = acc;
}

__global__ __launch_bounds__(256) void colsum_reduce_kernel(int sel) {
    const float* part = sel ? g_part1 : g_part0;
    float* cs = sel ? g_cs1 : g_cs0;
    int idx = blockIdx.x * 256 + threadIdx.x;   // < BB*DIMV = 6144
    float a = 0.f;
    #pragma unroll
    for (int z = 0; z < 16; z++) a += part[(size_t)z * BB * DIMV + idx];
    cs[idx] = a;
}

// ---------------------------------------------------------------------------
// W transpose: WT[k][j] = W[j][k]
// ---------------------------------------------------------------------------
__global__ void transpose_kernel(const float* __restrict__ W, int sel) {
    float* WT = sel ? g_WT1 : g_WT0;
    __shared__ float t[32][33];
    int k0 = blockIdx.x * 32, j0 = blockIdx.y * 32;
    int tx = threadIdx.x, ty = threadIdx.y;   // 32 x 8
    #pragma unroll
    for (int r = 0; r < 32; r += 8)
        t[ty + r][tx] = W[(size_t)(j0 + ty + r) * DIMV + k0 + tx];
    __syncthreads();
    #pragma unroll
    for (int r = 0; r < 32; r += 8)
        WT[(size_t)(k0 + ty + r) * DIMV + j0 + tx] = t[tx][ty + r];
}

// ---------------------------------------------------------------------------
// Shared GEMM microkernel: 8x8 per thread, 16x16 threads, rank-1 over BK
// ---------------------------------------------------------------------------
__device__ __forceinline__ void gemm_compute(const float (*As)[LDSM], const float (*Bs)[LDSM],
                                             float acc[8][8], int tx, int ty) {
    #pragma unroll
    for (int kk = 0; kk < BK; kk++) {
        float a[8], b[8];
        *(float4*)(a)     = *(const float4*)(&As[kk][ty * 4]);
        *(float4*)(a + 4) = *(const float4*)(&As[kk][ty * 4 + 64]);
        *(float4*)(b)     = *(const float4*)(&Bs[kk][tx * 4]);
        *(float4*)(b + 4) = *(const float4*)(&Bs[kk][tx * 4 + 64]);
        #pragma unroll
        for (int i = 0; i < 8; i++)
            #pragma unroll
            for (int j = 0; j < 8; j++)
                acc[i][j] = fmaf(a[i], b[j], acc[i][j]);
    }
}

// ---------------------------------------------------------------------------
// M[b] = (H[b]^T H[b]) * diag(1/cs)   — TN GEMM, K = 2048
// grid (6, 6, 16): z = s*8 + b
// ---------------------------------------------------------------------------
__global__ __launch_bounds__(256, 2) void gemm_tn_kernel() {
    int s = blockIdx.z >> 3;
    int b = blockIdx.z & 7;
    const float* A  = (s ? g_H1 : g_H0) + (size_t)b * NT * DIMV;
    const float* cs = (s ? g_cs1 : g_cs0) + b * DIMV;
    float* Mo = (s ? g_M1 : g_M0) + (size_t)b * DIMV * DIMV;
    int i0 = blockIdx.y * BM, j0 = blockIdx.x * BN;

    __shared__ float As[BK][LDSM], Bs[BK][LDSM];
    float acc[8][8];
    #pragma unroll
    for (int i = 0; i < 8; i++)
        #pragma unroll
        for (int j = 0; j < 8; j++) acc[i][j] = 0.f;

    int tid = threadIdx.x, tx = tid & 15, ty = tid >> 4;
    for (int k0 = 0; k0 < NT; k0 += BK) {
        #pragma unroll
        for (int rep = 0; rep < 2; rep++) {
            int slot = tid + rep * 256;
            int k = slot >> 5, c4 = (slot & 31) << 2;
            const float* src = A + (size_t)(k0 + k) * DIMV;
            *(float4*)(&As[k][c4]) = *(const float4*)(src + i0 + c4);
            *(float4*)(&Bs[k][c4]) = *(const float4*)(src + j0 + c4);
        }
        __syncthreads();
        gemm_compute(As, Bs, acc, tx, ty);
        __syncthreads();
    }

    float rc[8];
    #pragma unroll
    for (int j = 0; j < 8; j++) {
        int c = j0 + tx * 4 + (j & 3) + ((j >> 2) << 6);
        rc[j] = 1.0f / cs[c];
    }
    #pragma unroll
    for (int i = 0; i < 8; i++) {
        int r = i0 + ty * 4 + (i & 3) + ((i >> 2) << 6);
        float* row = Mo + (size_t)r * DIMV + j0;
        float4 v0 = make_float4(acc[i][0] * rc[0], acc[i][1] * rc[1], acc[i][2] * rc[2], acc[i][3] * rc[3]);
        float4 v1 = make_float4(acc[i][4] * rc[4], acc[i][5] * rc[5], acc[i][6] * rc[6], acc[i][7] * rc[7]);
        *(float4*)(row + tx * 4)      = v0;
        *(float4*)(row + tx * 4 + 64) = v1;
    }
}

// ---------------------------------------------------------------------------
// C[b] = f * (M1[b] @ W1^T + M2[b] @ W2^T)   — NN GEMM, two K=768 passes
// grid (6, 6, 8)
// ---------------------------------------------------------------------------
__global__ __launch_bounds__(256, 2) void gemm_c_kernel(const float* __restrict__ wg) {
    int b = blockIdx.z;
    int i0 = blockIdx.y * BM, j0 = blockIdx.x * BN;

    __shared__ float As[BK][LDSM], Bs[BK][LDSM];
    float acc[8][8];
    #pragma unroll
    for (int i = 0; i < 8; i++)
        #pragma unroll
        for (int j = 0; j < 8; j++) acc[i][j] = 0.f;

    int tid = threadIdx.x, tx = tid & 15, ty = tid >> 4;
    #pragma unroll 1
    for (int pass = 0; pass < 2; pass++) {
        const float* A    = (pass ? g_M1 : g_M0) + (size_t)b * DIMV * DIMV;
        const float* Bmat = pass ? g_WT1 : g_WT0;
        for (int k0 = 0; k0 < DIMV; k0 += BK) {
            #pragma unroll
            for (int rep = 0; rep < 2; rep++) {
                int slot = tid + rep * 256;
                int ia = slot >> 2, kq = (slot & 3) << 2;
                float4 va = *(const float4*)(A + (size_t)(i0 + ia) * DIMV + k0 + kq);
                As[kq + 0][ia] = va.x; As[kq + 1][ia] = va.y;
                As[kq + 2][ia] = va.z; As[kq + 3][ia] = va.w;
                int kb = slot >> 5, j4 = (slot & 31) << 2;
                *(float4*)(&Bs[kb][j4]) = *(const float4*)(Bmat + (size_t)(k0 + kb) * DIMV + j0 + j4);
            }
            __syncthreads();
            gemm_compute(As, Bs, acc, tx, ty);
            __syncthreads();
        }
    }

    float f = 1.0f / (1.0f + expf(-wg[0]));
    float* Co = g_Cmat + (size_t)b * DIMV * DIMV;
    #pragma unroll
    for (int i = 0; i < 8; i++) {
        int r = i0 + ty * 4 + (i & 3) + ((i >> 2) << 6);
        float* row = Co + (size_t)r * DIMV + j0;
        float4 v0 = make_float4(f * acc[i][0], f * acc[i][1], f * acc[i][2], f * acc[i][3]);
        float4 v1 = make_float4(f * acc[i][4], f * acc[i][5], f * acc[i][6], f * acc[i][7]);
        *(float4*)(row + tx * 4)      = v0;
        *(float4*)(row + tx * 4 + 64) = v1;
    }
}

// ---------------------------------------------------------------------------
// out[b] = x[b] @ C[b] + f*(b1+b2) + x[b]   — NN GEMM, K=768
// grid (6, 16, 8)
// ---------------------------------------------------------------------------
__global__ __launch_bounds__(256, 2) void gemm_final_kernel(const float* __restrict__ x,
                                                            const float* __restrict__ b1,
                                                            const float* __restrict__ b2,
                                                            const float* __restrict__ wg,
                                                            float* __restrict__ out) {
    int b = blockIdx.z;
    int i0 = blockIdx.y * BM;
    int j0 = blockIdx.x * BN;
    const float* A    = x + (size_t)b * NT * DIMV;
    const float* Bmat = g_Cmat + (size_t)b * DIMV * DIMV;

    __shared__ float As[BK][LDSM], Bs[BK][LDSM];
    float acc[8][8];
    #pragma unroll
    for (int i = 0; i < 8; i++)
        #pragma unroll
        for (int j = 0; j < 8; j++) acc[i][j] = 0.f;

    int tid = threadIdx.x, tx = tid & 15, ty = tid >> 4;
    for (int k0 = 0; k0 < DIMV; k0 += BK) {
        #pragma unroll
        for (int rep = 0; rep < 2; rep++) {
            int slot = tid + rep * 256;
            int ia = slot >> 2, kq = (slot & 3) << 2;
            float4 va = *(const float4*)(A + (size_t)(i0 + ia) * DIMV + k0 + kq);
            As[kq + 0][ia] = va.x; As[kq + 1][ia] = va.y;
            As[kq + 2][ia] = va.z; As[kq + 3][ia] = va.w;
            int kb = slot >> 5, j4 = (slot & 31) << 2;
            *(float4*)(&Bs[kb][j4]) = *(const float4*)(Bmat + (size_t)(k0 + kb) * DIMV + j0 + j4);
        }
        __syncthreads();
        gemm_compute(As, Bs, acc, tx, ty);
        __syncthreads();
    }

    float f = 1.0f / (1.0f + expf(-wg[0]));
    float bias[8];
    #pragma unroll
    for (int j = 0; j < 8; j++) {
        int c = j0 + tx * 4 + (j & 3) + ((j >> 2) << 6);
        bias[j] = f * (b1[c] + b2[c]);
    }
    #pragma unroll
    for (int i = 0; i < 8; i++) {
        int r = i0 + ty * 4 + (i & 3) + ((i >> 2) << 6);
        const float* xr = A + (size_t)r * DIMV + j0;
        float* orow = out + ((size_t)b * NT + r) * DIMV + j0;
        float4 x0 = *(const float4*)(xr + tx * 4);
        float4 x1 = *(const float4*)(xr + tx * 4 + 64);
        float4 v0 = make_float4(acc[i][0] + bias[0] + x0.x, acc[i][1] + bias[1] + x0.y,
                                acc[i][2] + bias[2] + x0.z, acc[i][3] + bias[3] + x0.w);
        float4 v1 = make_float4(acc[i][4] + bias[4] + x1.x, acc[i][5] + bias[5] + x1.y,
                                acc[i][6] + bias[6] + x1.z, acc[i][7] + bias[7] + x1.w);
        *(float4*)(orow + tx * 4)      = v0;
        *(float4*)(orow + tx * 4 + 64) = v1;
    }
}

// ---------------------------------------------------------------------------
// Launch
// ---------------------------------------------------------------------------
extern "C" void kernel_launch(void* const* d_in, const int* in_sizes, int n_in,
                              void* d_out, int out_size) {
    (void)in_sizes; (void)n_in; (void)out_size;
    const float* x  = (const float*)d_in[0];
    const float* x2 = (const float*)d_in[1];
    const float* x3 = (const float*)d_in[2];
    const float* W1 = (const float*)d_in[3];
    const float* b1 = (const float*)d_in[4];
    const float* W2 = (const float*)d_in[5];
    const float* b2 = (const float*)d_in[6];
    const float* wg = (const float*)d_in[7];
    float* out = (float*)d_out;

    row_softmax_kernel<<<BB * NT, 256>>>(x2, 0);
    row_softmax_kernel<<<BB * NT, 256>>>(x3, 1);
    colsum_part_kernel<<<dim3(3, BB, 16), 256>>>(0);
    colsum_part_kernel<<<dim3(3, BB, 16), 256>>>(1);
    colsum_reduce_kernel<<<24, 256>>>(0);
    colsum_reduce_kernel<<<24, 256>>>(1);
    transpose_kernel<<<dim3(24, 24), dim3(32, 8)>>>(W1, 0);
    transpose_kernel<<<dim3(24, 24), dim3(32, 8)>>>(W2, 1);
    gemm_tn_kernel<<<dim3(6, 6, 16), 256>>>();
    gemm_c_kernel<<<dim3(6, 6, 8), 256>>>(wg);
    gemm_final_kernel<<<dim3(6, 16, 8), 256>>>(x, b1, b2, wg, out);
}

// round 10
// speedup vs baseline: 1.0001x; 1.0001x over previous
#include <cuda_runtime.h>

// Problem constants
#define DIMV 768
#define BB   8
#define NT   2048

// GEMM tiling
#define BM 128
#define BN 128
#define BK 16
#define LDSM 132   // BM + 4 pad: keeps 16B alignment, avoids bank conflicts

// ---------------------------------------------------------------------------
// Scratch (device globals: allocation-free per harness rules)
// ---------------------------------------------------------------------------
__device__ float g_H0[BB * NT * DIMV];       // H for x2: exp(x)/sqrt(rowsum)
__device__ float g_H1[BB * NT * DIMV];       // H for x3
__device__ float g_rs0[BB * NT];             // sqrt(rowsum_true) per row
__device__ float g_rs1[BB * NT];
__device__ float g_part0[16 * BB * DIMV];    // partial column sums
__device__ float g_part1[16 * BB * DIMV];
__device__ float g_cs0[BB * DIMV];           // colsum of exp(x2)
__device__ float g_cs1[BB * DIMV];
__device__ float g_M0[BB * DIMV * DIMV];     // M1 = key1^T query1
__device__ float g_M1[BB * DIMV * DIMV];     // M2
__device__ float g_WT0[DIMV * DIMV];         // W1 transposed
__device__ float g_WT1[DIMV * DIMV];         // W2 transposed
__device__ float g_Cmat[BB * DIMV * DIMV];   // f*(M1 W1^T + M2 W2^T)

// ---------------------------------------------------------------------------
// Row softmax -> H[m,d] = exp(x[m,d]) / sqrt(S[m]),  rs[m] = sqrt(S[m])
// (S = true rowsum of exp; computed max-shifted for safety)
// One block per row (768 elems, 256 threads, 3 per thread).
// ---------------------------------------------------------------------------
__global__ __launch_bounds__(256) void row_softmax_kernel(const float* __restrict__ x, int sel) {
    float* H  = sel ? g_H1  : g_H0;
    float* rs = sel ? g_rs1 : g_rs0;
    size_t row = blockIdx.x;
    const float* xr = x + row * DIMV;
    int tid = threadIdx.x;

    float v0 = xr[tid], v1 = xr[tid + 256], v2 = xr[tid + 512];
    float m = fmaxf(v0, fmaxf(v1, v2));

    __shared__ float red[8];
    #pragma unroll
    for (int o = 16; o > 0; o >>= 1) m = fmaxf(m, __shfl_xor_sync(0xffffffffu, m, o));
    if ((tid & 31) == 0) red[tid >> 5] = m;
    __syncthreads();
    float bm = red[0];
    #pragma unroll
    for (int i = 1; i < 8; i++) bm = fmaxf(bm, red[i]);

    float e0 = expf(v0 - bm), e1 = expf(v1 - bm), e2 = expf(v2 - bm);
    float s = e0 + e1 + e2;
    #pragma unroll
    for (int o = 16; o > 0; o >>= 1) s += __shfl_xor_sync(0xffffffffu, s, o);
    __syncthreads();                       // before reusing red[]
    if ((tid & 31) == 0) red[tid >> 5] = s;
    __syncthreads();
    float S = 0.f;
    #pragma unroll
    for (int i = 0; i < 8; i++) S += red[i];

    // H = e * exp(bm/2)/sqrt(S_shift);  rs = exp(bm/2)*sqrt(S_shift)
    float half = expf(0.5f * bm);
    float scale = half * rsqrtf(S);
    float* hr = H + row * DIMV;
    hr[tid]       = e0 * scale;
    hr[tid + 256] = e1 * scale;
    hr[tid + 512] = e2 * scale;
    if (tid == 0) rs[row] = half * sqrtf(S);
}

// ---------------------------------------------------------------------------
// Column sums of exp(x) = sum_m H[m,d]*rs[m].  Partial over 128-row chunks.
// grid (3, BB, 16), 256 threads
// ---------------------------------------------------------------------------
__global__ __launch_bounds__(256) void colsum_part_kernel(int sel) {
    const float* H  = sel ? g_H1  : g_H0;
    const float* rs = sel ? g_rs1 : g_rs0;
    float* part = sel ? g_part1 : g_part0;
    int d = blockIdx.x * 256 + threadIdx.x;
    int b = blockIdx.y, z = blockIdx.z;
    size_t rowbase = (size_t)b * NT + (size_t)z * 128;
    const float* hp = H + rowbase * DIMV + d;
    const float* rp = rs + rowbase;
    float acc = 0.f;
    #pragma unroll 4
    for (int m = 0; m < 128; m++)
        acc = fmaf(hp[(size_t)m * DIMV], rp[m], acc);
    part[((size_t)z * BB + b) * DIMV + d] = acc;
}

__global__ __launch_bounds__(256) void colsum_reduce_kernel(int sel) {
    const float* part = sel ? g_part1 : g_part0;
    float* cs = sel ? g_cs1 : g_cs0;
    int idx = blockIdx.x * 256 + threadIdx.x;   // < BB*DIMV = 6144
    float a = 0.f;
    #pragma unroll
    for (int z = 0; z < 16; z++) a += part[(size_t)z * BB * DIMV + idx];
    cs[idx] = a;
}

// ---------------------------------------------------------------------------
// W transpose: WT[k][j] = W[j][k]
// ---------------------------------------------------------------------------
__global__ void transpose_kernel(const float* __restrict__ W, int sel) {
    float* WT = sel ? g_WT1 : g_WT0;
    __shared__ float t[32][33];
    int k0 = blockIdx.x * 32, j0 = blockIdx.y * 32;
    int tx = threadIdx.x, ty = threadIdx.y;   // 32 x 8
    #pragma unroll
    for (int r = 0; r < 32; r += 8)
        t[ty + r][tx] = W[(size_t)(j0 + ty + r) * DIMV + k0 + tx];
    __syncthreads();
    #pragma unroll
    for (int r = 0; r < 32; r += 8)
        WT[(size_t)(k0 + ty + r) * DIMV + j0 + tx] = t[tx][ty + r];
}

// ---------------------------------------------------------------------------
// Shared GEMM microkernel: 8x8 per thread, 16x16 threads, rank-1 over BK
// ---------------------------------------------------------------------------
__device__ __forceinline__ void gemm_compute(const float (*As)[LDSM], const float (*Bs)[LDSM],
                                             float acc[8][8], int tx, int ty) {
    #pragma unroll
    for (int kk = 0; kk < BK; kk++) {
        float a[8], b[8];
        *(float4*)(a)     = *(const float4*)(&As[kk][ty * 4]);
        *(float4*)(a + 4) = *(const float4*)(&As[kk][ty * 4 + 64]);
        *(float4*)(b)     = *(const float4*)(&Bs[kk][tx * 4]);
        *(float4*)(b + 4) = *(const float4*)(&Bs[kk][tx * 4 + 64]);
        #pragma unroll
        for (int i = 0; i < 8; i++)
            #pragma unroll
            for (int j = 0; j < 8; j++)
                acc[i][j] = fmaf(a[i], b[j], acc[i][j]);
    }
}

// ---------------------------------------------------------------------------
// M[b] = (H[b]^T H[b]) * diag(1/cs)   — TN GEMM, K = 2048
// grid (6, 6, 16): z = s*8 + b
// ---------------------------------------------------------------------------
__global__ __launch_bounds__(256, 2) void gemm_tn_kernel() {
    int s = blockIdx.z >> 3;
    int b = blockIdx.z & 7;
    const float* A  = (s ? g_H1 : g_H0) + (size_t)b * NT * DIMV;
    const float* cs = (s ? g_cs1 : g_cs0) + b * DIMV;
    float* Mo = (s ? g_M1 : g_M0) + (size_t)b * DIMV * DIMV;
    int i0 = blockIdx.y * BM, j0 = blockIdx.x * BN;

    __shared__ float As[BK][LDSM], Bs[BK][LDSM];
    float acc[8][8];
    #pragma unroll
    for (int i = 0; i < 8; i++)
        #pragma unroll
        for (int j = 0; j < 8; j++) acc[i][j] = 0.f;

    int tid = threadIdx.x, tx = tid & 15, ty = tid >> 4;
    for (int k0 = 0; k0 < NT; k0 += BK) {
        #pragma unroll
        for (int rep = 0; rep < 2; rep++) {
            int slot = tid + rep * 256;
            int k = slot >> 5, c4 = (slot & 31) << 2;
            const float* src = A + (size_t)(k0 + k) * DIMV;
            *(float4*)(&As[k][c4]) = *(const float4*)(src + i0 + c4);
            *(float4*)(&Bs[k][c4]) = *(const float4*)(src + j0 + c4);
        }
        __syncthreads();
        gemm_compute(As, Bs, acc, tx, ty);
        __syncthreads();
    }

    float rc[8];
    #pragma unroll
    for (int j = 0; j < 8; j++) {
        int c = j0 + tx * 4 + (j & 3) + ((j >> 2) << 6);
        rc[j] = 1.0f / cs[c];
    }
    #pragma unroll
    for (int i = 0; i < 8; i++) {
        int r = i0 + ty * 4 + (i & 3) + ((i >> 2) << 6);
        float* row = Mo + (size_t)r * DIMV + j0;
        float4 v0 = make_float4(acc[i][0] * rc[0], acc[i][1] * rc[1], acc[i][2] * rc[2], acc[i][3] * rc[3]);
        float4 v1 = make_float4(acc[i][4] * rc[4], acc[i][5] * rc[5], acc[i][6] * rc[6], acc[i][7] * rc[7]);
        *(float4*)(row + tx * 4)      = v0;
        *(float4*)(row + tx * 4 + 64) = v1;
    }
}

// ---------------------------------------------------------------------------
// C[b] = f * (M1[b] @ W1^T + M2[b] @ W2^T)   — NN GEMM, two K=768 passes
// grid (6, 6, 8)
// ---------------------------------------------------------------------------
__global__ __launch_bounds__(256, 2) void gemm_c_kernel(const float* __restrict__ wg) {
    int b = blockIdx.z;
    int i0 = blockIdx.y * BM, j0 = blockIdx.x * BN;

    __shared__ float As[BK][LDSM], Bs[BK][LDSM];
    float acc[8][8];
    #pragma unroll
    for (int i = 0; i < 8; i++)
        #pragma unroll
        for (int j = 0; j < 8; j++) acc[i][j] = 0.f;

    int tid = threadIdx.x, tx = tid & 15, ty = tid >> 4;
    #pragma unroll 1
    for (int pass = 0; pass < 2; pass++) {
        const float* A    = (pass ? g_M1 : g_M0) + (size_t)b * DIMV * DIMV;
        const float* Bmat = pass ? g_WT1 : g_WT0;
        for (int k0 = 0; k0 < DIMV; k0 += BK) {
            #pragma unroll
            for (int rep = 0; rep < 2; rep++) {
                int slot = tid + rep * 256;
                int ia = slot >> 2, kq = (slot & 3) << 2;
                float4 va = *(const float4*)(A + (size_t)(i0 + ia) * DIMV + k0 + kq);
                As[kq + 0][ia] = va.x; As[kq + 1][ia] = va.y;
                As[kq + 2][ia] = va.z; As[kq + 3][ia] = va.w;
                int kb = slot >> 5, j4 = (slot & 31) << 2;
                *(float4*)(&Bs[kb][j4]) = *(const float4*)(Bmat + (size_t)(k0 + kb) * DIMV + j0 + j4);
            }
            __syncthreads();
            gemm_compute(As, Bs, acc, tx, ty);
            __syncthreads();
        }
    }

    float f = 1.0f / (1.0f + expf(-wg[0]));
    float* Co = g_Cmat + (size_t)b * DIMV * DIMV;
    #pragma unroll
    for (int i = 0; i < 8; i++) {
        int r = i0 + ty * 4 + (i & 3) + ((i >> 2) << 6);
        float* row = Co + (size_t)r * DIMV + j0;
        float4 v0 = make_float4(f * acc[i][0], f * acc[i][1], f * acc[i][2], f * acc[i][3]);
        float4 v1 = make_float4(f * acc[i][4], f * acc[i][5], f * acc[i][6], f * acc[i][7]);
        *(float4*)(row + tx * 4)      = v0;
        *(float4*)(row + tx * 4 + 64) = v1;
    }
}

// ---------------------------------------------------------------------------
// out[b] = x[b] @ C[b] + f*(b1+b2) + x[b]   — NN GEMM, K=768
// grid (6, 16, 8)
// ---------------------------------------------------------------------------
__global__ __launch_bounds__(256, 2) void gemm_final_kernel(const float* __restrict__ x,
                                                            const float* __restrict__ b1,
                                                            const float* __restrict__ b2,
                                                            const float* __restrict__ wg,
                                                            float* __restrict__ out) {
    int b = blockIdx.z;
    int i0 = blockIdx.y * BM;
    int j0 = blockIdx.x * BN;
    const float* A    = x + (size_t)b * NT * DIMV;
    const float* Bmat = g_Cmat + (size_t)b * DIMV * DIMV;

    __shared__ float As[BK][LDSM], Bs[BK][LDSM];
    float acc[8][8];
    #pragma unroll
    for (int i = 0; i < 8; i++)
        #pragma unroll
        for (int j = 0; j < 8; j++) acc[i][j] = 0.f;

    int tid = threadIdx.x, tx = tid & 15, ty = tid >> 4;
    for (int k0 = 0; k0 < DIMV; k0 += BK) {
        #pragma unroll
        for (int rep = 0; rep < 2; rep++) {
            int slot = tid + rep * 256;
            int ia = slot >> 2, kq = (slot & 3) << 2;
            float4 va = *(const float4*)(A + (size_t)(i0 + ia) * DIMV + k0 + kq);
            As[kq + 0][ia] = va.x; As[kq + 1][ia] = va.y;
            As[kq + 2][ia] = va.z; As[kq + 3][ia] = va.w;
            int kb = slot >> 5, j4 = (slot & 31) << 2;
            *(float4*)(&Bs[kb][j4]) = *(const float4*)(Bmat + (size_t)(k0 + kb) * DIMV + j0 + j4);
        }
        __syncthreads();
        gemm_compute(As, Bs, acc, tx, ty);
        __syncthreads();
    }

    float f = 1.0f / (1.0f + expf(-wg[0]));
    float bias[8];
    #pragma unroll
    for (int j = 0; j < 8; j++) {
        int c = j0 + tx * 4 + (j & 3) + ((j >> 2) << 6);
        bias[j] = f * (b1[c] + b2[c]);
    }
    #pragma unroll
    for (int i = 0; i < 8; i++) {
        int r = i0 + ty * 4 + (i & 3) + ((i >> 2) << 6);
        const float* xr = A + (size_t)r * DIMV + j0;
        float* orow = out + ((size_t)b * NT + r) * DIMV + j0;
        float4 x0 = *(const float4*)(xr + tx * 4);
        float4 x1 = *(const float4*)(xr + tx * 4 + 64);
        float4 v0 = make_float4(acc[i][0] + bias[0] + x0.x, acc[i][1] + bias[1] + x0.y,
                                acc[i][2] + bias[2] + x0.z, acc[i][3] + bias[3] + x0.w);
        float4 v1 = make_float4(acc[i][4] + bias[4] + x1.x, acc[i][5] + bias[5] + x1.y,
                                acc[i][6] + bias[6] + x1.z, acc[i][7] + bias[7] + x1.w);
        *(float4*)(orow + tx * 4)      = v0;
        *(float4*)(orow + tx * 4 + 64) = v1;
    }
}

// ---------------------------------------------------------------------------
// Launch
// ---------------------------------------------------------------------------
extern "C" void kernel_launch(void* const* d_in, const int* in_sizes, int n_in,
                              void* d_out, int out_size) {
    (void)in_sizes; (void)n_in; (void)out_size;
    const float* x  = (const float*)d_in[0];
    const float* x2 = (const float*)d_in[1];
    const float* x3 = (const float*)d_in[2];
    const float* W1 = (const float*)d_in[3];
    const float* b1 = (const float*)d_in[4];
    const float* W2 = (const float*)d_in[5];
    const float* b2 = (const float*)d_in[6];
    const float* wg = (const float*)d_in[7];
    float* out = (float*)d_out;

    row_softmax_kernel<<<BB * NT, 256>>>(x2, 0);
    row_softmax_kernel<<<BB * NT, 256>>>(x3, 1);
    colsum_part_kernel<<<dim3(3, BB, 16), 256>>>(0);
    colsum_part_kernel<<<dim3(3, BB, 16), 256>>>(1);
    colsum_reduce_kernel<<<24, 256>>>(0);
    colsum_reduce_kernel<<<24, 256>>>(1);
    transpose_kernel<<<dim3(24, 24), dim3(32, 8)>>>(W1, 0);
    transpose_kernel<<<dim3(24, 24), dim3(32, 8)>>>(W2, 1);
    gemm_tn_kernel<<<dim3(6, 6, 16), 256>>>();
    gemm_c_kernel<<<dim3(6, 6, 8), 256>>>(wg);
    gemm_final_kernel<<<dim3(6, 16, 8), 256>>>(x, b1, b2, wg, out);
}

// round 13
// speedup vs baseline: 2.1195x; 2.1193x over previous
#include <cuda_runtime.h>
#include <cstdint>

// Problem constants
#define DIMV 768
#define BB   8
#define NT   2048

// GEMM tiling
#define BM 128
#define BN 128
#define BK 16
#define LDSM 136   // BM + 8 pad: k-row stride = 8 banks -> conflict-free tf32 fragment LDS

// ---------------------------------------------------------------------------
// Scratch (device globals: allocation-free per harness rules)
// ---------------------------------------------------------------------------
__device__ float g_H0[BB * NT * DIMV];       // H for x2 (tf32-rounded): exp(x)/sqrt(rowsum)
__device__ float g_H1[BB * NT * DIMV];       // H for x3 (tf32-rounded)
__device__ float g_rs0[BB * NT];             // sqrt(rowsum_true) per row
__device__ float g_rs1[BB * NT];
__device__ float g_part0[16 * BB * DIMV];    // partial column sums
__device__ float g_part1[16 * BB * DIMV];
__device__ float g_cs0[BB * DIMV];           // colsum of exp(x2)
__device__ float g_cs1[BB * DIMV];
__device__ float g_M0[BB * DIMV * DIMV];     // M1 (tf32-rounded)
__device__ float g_M1[BB * DIMV * DIMV];     // M2 (tf32-rounded)
__device__ float g_WT0[DIMV * DIMV];         // W1^T (tf32-rounded)
__device__ float g_WT1[DIMV * DIMV];         // W2^T (tf32-rounded)
__device__ float g_Cmat[BB * DIMV * DIMV];   // f*(M1 W1^T + M2 W2^T) (tf32-rounded)

// ---------------------------------------------------------------------------
// tf32 helpers
// ---------------------------------------------------------------------------
__device__ __forceinline__ float tf32r(float x) {
    uint32_t u;
    asm("cvt.rna.tf32.f32 %0, %1;" : "=r"(u) : "f"(x));
    return __uint_as_float(u);
}

__device__ __forceinline__ void mma8(float* c, uint32_t a0, uint32_t a1, uint32_t a2, uint32_t a3,
                                     uint32_t b0, uint32_t b1) {
    asm volatile("mma.sync.aligned.m16n8k8.row.col.f32.tf32.tf32.f32 "
                 "{%0,%1,%2,%3}, {%4,%5,%6,%7}, {%8,%9}, {%0,%1,%2,%3};"
                 : "+f"(c[0]), "+f"(c[1]), "+f"(c[2]), "+f"(c[3])
                 : "r"(a0), "r"(a1), "r"(a2), "r"(a3), "r"(b0), "r"(b1));
}

// ---------------------------------------------------------------------------
// Row softmax -> H[m,d] = tf32_round( exp(x[m,d]) / sqrt(S[m]) ), rs[m]=sqrt(S[m])
// ---------------------------------------------------------------------------
__global__ __launch_bounds__(256) void row_softmax_kernel(const float* __restrict__ x, int sel) {
    float* H  = sel ? g_H1  : g_H0;
    float* rs = sel ? g_rs1 : g_rs0;
    size_t row = blockIdx.x;
    const float* xr = x + row * DIMV;
    int tid = threadIdx.x;

    float v0 = xr[tid], v1 = xr[tid + 256], v2 = xr[tid + 512];
    float m = fmaxf(v0, fmaxf(v1, v2));

    __shared__ float red[8];
    #pragma unroll
    for (int o = 16; o > 0; o >>= 1) m = fmaxf(m, __shfl_xor_sync(0xffffffffu, m, o));
    if ((tid & 31) == 0) red[tid >> 5] = m;
    __syncthreads();
    float bm = red[0];
    #pragma unroll
    for (int i = 1; i < 8; i++) bm = fmaxf(bm, red[i]);

    float e0 = expf(v0 - bm), e1 = expf(v1 - bm), e2 = expf(v2 - bm);
    float s = e0 + e1 + e2;
    #pragma unroll
    for (int o = 16; o > 0; o >>= 1) s += __shfl_xor_sync(0xffffffffu, s, o);
    __syncthreads();
    if ((tid & 31) == 0) red[tid >> 5] = s;
    __syncthreads();
    float S = 0.f;
    #pragma unroll
    for (int i = 0; i < 8; i++) S += red[i];

    float half = expf(0.5f * bm);
    float scale = half * rsqrtf(S);
    float* hr = H + row * DIMV;
    hr[tid]       = tf32r(e0 * scale);
    hr[tid + 256] = tf32r(e1 * scale);
    hr[tid + 512] = tf32r(e2 * scale);
    if (tid == 0) rs[row] = half * sqrtf(S);
}

// ---------------------------------------------------------------------------
// Column sums of exp(x) = sum_m H[m,d]*rs[m]. float4 per thread over d.
// grid (BB, 16), 192 threads (192*4 = 768 = DIMV)
// ---------------------------------------------------------------------------
__global__ __launch_bounds__(192) void colsum_part_kernel(int sel) {
    const float* H  = sel ? g_H1  : g_H0;
    const float* rs = sel ? g_rs1 : g_rs0;
    float* part = sel ? g_part1 : g_part0;
    int d = threadIdx.x * 4;
    int b = blockIdx.x, z = blockIdx.y;
    size_t rowbase = (size_t)b * NT + (size_t)z * 128;
    const float4* hp = (const float4*)(H + rowbase * DIMV + d);
    const float* rp = rs + rowbase;
    float4 acc = make_float4(0.f, 0.f, 0.f, 0.f);
    #pragma unroll 4
    for (int m = 0; m < 128; m++) {
        float4 h = hp[(size_t)m * (DIMV / 4)];
        float r = rp[m];
        acc.x = fmaf(h.x, r, acc.x);
        acc.y = fmaf(h.y, r, acc.y);
        acc.z = fmaf(h.z, r, acc.z);
        acc.w = fmaf(h.w, r, acc.w);
    }
    *(float4*)(part + ((size_t)z * BB + b) * DIMV + d) = acc;
}

__global__ __launch_bounds__(256) void colsum_reduce_kernel(int sel) {
    const float* part = sel ? g_part1 : g_part0;
    float* cs = sel ? g_cs1 : g_cs0;
    int idx = blockIdx.x * 256 + threadIdx.x;   // < BB*DIMV = 6144
    float a = 0.f;
    #pragma unroll
    for (int z = 0; z < 16; z++) a += part[(size_t)z * BB * DIMV + idx];
    cs[idx] = a;
}

// ---------------------------------------------------------------------------
// W transpose (tf32-rounded): WT[k][j] = W[j][k]
// ---------------------------------------------------------------------------
__global__ void transpose_kernel(const float* __restrict__ W, int sel) {
    float* WT = sel ? g_WT1 : g_WT0;
    __shared__ float t[32][33];
    int k0 = blockIdx.x * 32, j0 = blockIdx.y * 32;
    int tx = threadIdx.x, ty = threadIdx.y;   // 32 x 8
    #pragma unroll
    for (int r = 0; r < 32; r += 8)
        t[ty + r][tx] = W[(size_t)(j0 + ty + r) * DIMV + k0 + tx];
    __syncthreads();
    #pragma unroll
    for (int r = 0; r < 32; r += 8)
        WT[(size_t)(k0 + ty + r) * DIMV + j0 + tx] = tf32r(t[tx][ty + r]);
}

// ---------------------------------------------------------------------------
// tf32 MMA block compute: 8 warps (2M x 4N), warp tile 64x32,
// per warp: 4 Mtiles (m16) x 4 Ntiles (n8), m16n8k8 fragments.
// As[k][m], Bs[k][n] hold tf32-valued floats.
// ---------------------------------------------------------------------------
__device__ __forceinline__ void mma_compute(const float (*As)[LDSM], const float (*Bs)[LDSM],
                                            float acc[4][4][4], int wm, int wn, int lr, int lc) {
    #pragma unroll
    for (int ks = 0; ks < BK; ks += 8) {
        uint32_t a[4][4], b[4][2];
        #pragma unroll
        for (int i = 0; i < 4; i++) {
            int m0 = wm * 64 + i * 16 + lr;
            a[i][0] = __float_as_uint(As[ks + lc][m0]);
            a[i][1] = __float_as_uint(As[ks + lc][m0 + 8]);
            a[i][2] = __float_as_uint(As[ks + lc + 4][m0]);
            a[i][3] = __float_as_uint(As[ks + lc + 4][m0 + 8]);
        }
        #pragma unroll
        for (int j = 0; j < 4; j++) {
            int n0 = wn * 32 + j * 8 + lr;
            b[j][0] = __float_as_uint(Bs[ks + lc][n0]);
            b[j][1] = __float_as_uint(Bs[ks + lc + 4][n0]);
        }
        #pragma unroll
        for (int i = 0; i < 4; i++)
            #pragma unroll
            for (int j = 0; j < 4; j++)
                mma8(acc[i][j], a[i][0], a[i][1], a[i][2], a[i][3], b[j][0], b[j][1]);
    }
}

#define ACC_ZERO(acc)                              \
    _Pragma("unroll")                              \
    for (int i = 0; i < 4; i++)                    \
        _Pragma("unroll")                          \
        for (int j = 0; j < 4; j++)                \
            _Pragma("unroll")                      \
            for (int q = 0; q < 4; q++) acc[i][j][q] = 0.f;

// ---------------------------------------------------------------------------
// M[b] = (H[b]^T H[b]) * diag(1/cs)   — TN GEMM, K = 2048, tensor cores
// grid (6, 6, 16): z = s*8 + b
// ---------------------------------------------------------------------------
__global__ __launch_bounds__(256, 2) void gemm_tn_kernel() {
    int s = blockIdx.z >> 3;
    int b = blockIdx.z & 7;
    const float* A  = (s ? g_H1 : g_H0) + (size_t)b * NT * DIMV;
    const float* cs = (s ? g_cs1 : g_cs0) + b * DIMV;
    float* Mo = (s ? g_M1 : g_M0) + (size_t)b * DIMV * DIMV;
    int i0 = blockIdx.y * BM, j0 = blockIdx.x * BN;

    __shared__ float As[BK][LDSM], Bs[BK][LDSM];
    float acc[4][4][4];
    ACC_ZERO(acc);

    int tid = threadIdx.x;
    int w = tid >> 5, lane = tid & 31;
    int wm = w & 1, wn = w >> 1, lr = lane >> 2, lc = lane & 3;

    for (int k0 = 0; k0 < NT; k0 += BK) {
        #pragma unroll
        for (int rep = 0; rep < 2; rep++) {
            int slot = tid + rep * 256;
            int k = slot >> 5, c4 = (slot & 31) << 2;
            const float* src = A + (size_t)(k0 + k) * DIMV;
            *(float4*)(&As[k][c4]) = *(const float4*)(src + i0 + c4);  // H already tf32-valued
            *(float4*)(&Bs[k][c4]) = *(const float4*)(src + j0 + c4);
        }
        __syncthreads();
        mma_compute(As, Bs, acc, wm, wn, lr, lc);
        __syncthreads();
    }

    #pragma unroll
    for (int j = 0; j < 4; j++) {
        int c = j0 + wn * 32 + j * 8 + lc * 2;
        float rc0 = 1.0f / cs[c], rc1 = 1.0f / cs[c + 1];
        #pragma unroll
        for (int i = 0; i < 4; i++) {
            int r = i0 + wm * 64 + i * 16 + lr;
            float2 v0 = make_float2(tf32r(acc[i][j][0] * rc0), tf32r(acc[i][j][1] * rc1));
            float2 v1 = make_float2(tf32r(acc[i][j][2] * rc0), tf32r(acc[i][j][3] * rc1));
            *(float2*)(Mo + (size_t)r * DIMV + c)       = v0;
            *(float2*)(Mo + (size_t)(r + 8) * DIMV + c) = v1;
        }
    }
}

// ---------------------------------------------------------------------------
// C[b] = f * (M1[b] @ W1^T + M2[b] @ W2^T)   — NN GEMM, two K=768 passes
// grid (6, 6, 8)
// ---------------------------------------------------------------------------
__global__ __launch_bounds__(256, 2) void gemm_c_kernel(const float* __restrict__ wg) {
    int b = blockIdx.z;
    int i0 = blockIdx.y * BM, j0 = blockIdx.x * BN;

    __shared__ float As[BK][LDSM], Bs[BK][LDSM];
    float acc[4][4][4];
    ACC_ZERO(acc);

    int tid = threadIdx.x;
    int w = tid >> 5, lane = tid & 31;
    int wm = w & 1, wn = w >> 1, lr = lane >> 2, lc = lane & 3;

    #pragma unroll 1
    for (int pass = 0; pass < 2; pass++) {
        const float* A    = (pass ? g_M1 : g_M0) + (size_t)b * DIMV * DIMV;
        const float* Bmat = pass ? g_WT1 : g_WT0;
        for (int k0 = 0; k0 < DIMV; k0 += BK) {
            #pragma unroll
            for (int rep = 0; rep < 2; rep++) {
                int slot = tid + rep * 256;
                int ia = slot >> 2, kq = (slot & 3) << 2;
                float4 va = *(const float4*)(A + (size_t)(i0 + ia) * DIMV + k0 + kq);
                As[kq + 0][ia] = va.x; As[kq + 1][ia] = va.y;     // M pre-rounded
                As[kq + 2][ia] = va.z; As[kq + 3][ia] = va.w;
                int kb = slot >> 5, j4 = (slot & 31) << 2;
                *(float4*)(&Bs[kb][j4]) = *(const float4*)(Bmat + (size_t)(k0 + kb) * DIMV + j0 + j4);
            }
            __syncthreads();
            mma_compute(As, Bs, acc, wm, wn, lr, lc);
            __syncthreads();
        }
    }

    float f = 1.0f / (1.0f + expf(-wg[0]));
    float* Co = g_Cmat + (size_t)b * DIMV * DIMV;
    #pragma unroll
    for (int j = 0; j < 4; j++) {
        int c = j0 + wn * 32 + j * 8 + lc * 2;
        #pragma unroll
        for (int i = 0; i < 4; i++) {
            int r = i0 + wm * 64 + i * 16 + lr;
            float2 v0 = make_float2(tf32r(f * acc[i][j][0]), tf32r(f * acc[i][j][1]));
            float2 v1 = make_float2(tf32r(f * acc[i][j][2]), tf32r(f * acc[i][j][3]));
            *(float2*)(Co + (size_t)r * DIMV + c)       = v0;
            *(float2*)(Co + (size_t)(r + 8) * DIMV + c) = v1;
        }
    }
}

// ---------------------------------------------------------------------------
// out[b] = x[b] @ C[b] + f*(b1+b2) + x[b]   — NN GEMM, K=768
// grid (6, 16, 8)
// ---------------------------------------------------------------------------
__global__ __launch_bounds__(256, 2) void gemm_final_kernel(const float* __restrict__ x,
                                                            const float* __restrict__ b1,
                                                            const float* __restrict__ b2,
                                                            const float* __restrict__ wg,
                                                            float* __restrict__ out) {
    int b = blockIdx.z;
    int i0 = blockIdx.y * BM;
    int j0 = blockIdx.x * BN;
    const float* A    = x + (size_t)b * NT * DIMV;
    const float* Bmat = g_Cmat + (size_t)b * DIMV * DIMV;

    __shared__ float As[BK][LDSM], Bs[BK][LDSM];
    float acc[4][4][4];
    ACC_ZERO(acc);

    int tid = threadIdx.x;
    int w = tid >> 5, lane = tid & 31;
    int wm = w & 1, wn = w >> 1, lr = lane >> 2, lc = lane & 3;

    for (int k0 = 0; k0 < DIMV; k0 += BK) {
        #pragma unroll
        for (int rep = 0; rep < 2; rep++) {
            int slot = tid + rep * 256;
            int ia = slot >> 2, kq = (slot & 3) << 2;
            float4 va = *(const float4*)(A + (size_t)(i0 + ia) * DIMV + k0 + kq);
            As[kq + 0][ia] = tf32r(va.x); As[kq + 1][ia] = tf32r(va.y);   // x needs rounding
            As[kq + 2][ia] = tf32r(va.z); As[kq + 3][ia] = tf32r(va.w);
            int kb = slot >> 5, j4 = (slot & 31) << 2;
            *(float4*)(&Bs[kb][j4]) = *(const float4*)(Bmat + (size_t)(k0 + kb) * DIMV + j0 + j4);
        }
        __syncthreads();
        mma_compute(As, Bs, acc, wm, wn, lr, lc);
        __syncthreads();
    }

    float f = 1.0f / (1.0f + expf(-wg[0]));
    #pragma unroll
    for (int j = 0; j < 4; j++) {
        int c = j0 + wn * 32 + j * 8 + lc * 2;
        float bias0 = f * (b1[c] + b2[c]);
        float bias1 = f * (b1[c + 1] + b2[c + 1]);
        #pragma unroll
        for (int i = 0; i < 4; i++) {
            int r = i0 + wm * 64 + i * 16 + lr;
            const float* xr0 = A + (size_t)r * DIMV + c;
            const float* xr1 = A + (size_t)(r + 8) * DIMV + c;
            float2 x0 = *(const float2*)xr0;
            float2 x1 = *(const float2*)xr1;
            float2 v0 = make_float2(acc[i][j][0] + bias0 + x0.x, acc[i][j][1] + bias1 + x0.y);
            float2 v1 = make_float2(acc[i][j][2] + bias0 + x1.x, acc[i][j][3] + bias1 + x1.y);
            *(float2*)(out + ((size_t)b * NT + r) * DIMV + c)       = v0;
            *(float2*)(out + ((size_t)b * NT + r + 8) * DIMV + c)   = v1;
        }
    }
}

// ---------------------------------------------------------------------------
// Launch
// ---------------------------------------------------------------------------
extern "C" void kernel_launch(void* const* d_in, const int* in_sizes, int n_in,
                              void* d_out, int out_size) {
    (void)in_sizes; (void)n_in; (void)out_size;
    const float* x  = (const float*)d_in[0];
    const float* x2 = (const float*)d_in[1];
    const float* x3 = (const float*)d_in[2];
    const float* W1 = (const float*)d_in[3];
    const float* b1 = (const float*)d_in[4];
    const float* W2 = (const float*)d_in[5];
    const float* b2 = (const float*)d_in[6];
    const float* wg = (const float*)d_in[7];
    float* out = (float*)d_out;

    row_softmax_kernel<<<BB * NT, 256>>>(x2, 0);
    row_softmax_kernel<<<BB * NT, 256>>>(x3, 1);
    colsum_part_kernel<<<dim3(BB, 16), 192>>>(0);
    colsum_part_kernel<<<dim3(BB, 16), 192>>>(1);
    colsum_reduce_kernel<<<24, 256>>>(0);
    colsum_reduce_kernel<<<24, 256>>>(1);
    transpose_kernel<<<dim3(24, 24), dim3(32, 8)>>>(W1, 0);
    transpose_kernel<<<dim3(24, 24), dim3(32, 8)>>>(W2, 1);
    gemm_tn_kernel<<<dim3(6, 6, 16), 256>>>();
    gemm_c_kernel<<<dim3(6, 6, 8), 256>>>(wg);
    gemm_final_kernel<<<dim3(6, 16, 8), 256>>>(x, b1, b2, wg, out);
}